// round 14
// baseline (speedup 1.0000x reference)
#include <cuda_runtime.h>
#include <cuda_bf16.h>
#include <cstdint>

#define N_NODES  50000
#define N_EDGES  800000
#define HIDDEN   128
#define N_GRAPHS 256
#define N_CLASSES 10
#define ELL_CAP  96   // max in-degree capacity; P(deg>=96) ~ 1e-40 for Poisson(16)

// -------- device scratch (no allocations allowed) --------
__device__ __align__(16) float g_agg[N_NODES * HIDDEN];
__device__ __align__(16) float g_f1[N_NODES * HIDDEN];
__device__ __align__(16) float g_f2[N_NODES * HIDDEN];
__device__ int   g_deg[N_NODES];
__device__ int   g_ell[N_NODES * ELL_CAP];
__device__ __align__(16) float g_pooled[N_GRAPHS * HIDDEN];
// folded classifier: Wc = W2 @ Wl (128x10), bc = b2 @ Wl + bl (10)
__device__ __align__(16) float g_Wc[HIDDEN * N_CLASSES];
__device__ float g_bc[N_CLASSES];
// bf16 hi/lo split weights, TRANSPOSED to [n][k] (built once per call)
__device__ __align__(16) __nv_bfloat16 g_W1hT[HIDDEN * HIDDEN];
__device__ __align__(16) __nv_bfloat16 g_W1lT[HIDDEN * HIDDEN];
__device__ __align__(16) __nv_bfloat16 g_W2hT[HIDDEN * HIDDEN];
__device__ __align__(16) __nv_bfloat16 g_W2lT[HIDDEN * HIDDEN];

__device__ __forceinline__ const float* pick_feat(int sel, const float* x) {
    return sel == 0 ? x : (sel == 1 ? g_f1 : g_f2);
}
__device__ __forceinline__ float* pick_out(int sel) {
    return sel == 1 ? g_f1 : g_f2;
}
__device__ __forceinline__ int clamp_node(int v) {
    v = v < 0 ? 0 : v;
    return v >= N_NODES ? N_NODES - 1 : v;
}
__device__ __forceinline__ uint32_t smem_u32(const void* p) {
    uint32_t a;
    asm("{ .reg .u64 t; cvta.to.shared.u64 t, %1; cvt.u32.u64 %0, t; }" : "=r"(a) : "l"(p));
    return a;
}

// ---------------- merged prep: zero_deg + split_w + fold_wc ----------------
#define ZERO_BLKS 196
#define SPLIT_BLKS 64
__global__ void prep1_k(const float* __restrict__ W1, const float* __restrict__ W2,
                        const float* __restrict__ b2, const float* __restrict__ Wl,
                        const float* __restrict__ bl) {
    int b = blockIdx.x;
    int tid = threadIdx.x;
    if (b < ZERO_BLKS) {
        int i = b * 256 + tid;
        if (i < N_NODES) g_deg[i] = 0;
    } else if (b < ZERO_BLKS + SPLIT_BLKS) {
        int i = (b - ZERO_BLKS) * 256 + tid;   // i = n*128 + k
        int n = i >> 7, k = i & 127;
        float w = W1[k * HIDDEN + n];
        __nv_bfloat16 h = __float2bfloat16_rn(w);
        g_W1hT[i] = h;
        g_W1lT[i] = __float2bfloat16_rn(w - __bfloat162float(h));
        w = W2[k * HIDDEN + n];
        h = __float2bfloat16_rn(w);
        g_W2hT[i] = h;
        g_W2lT[i] = __float2bfloat16_rn(w - __bfloat162float(h));
    } else {
        int gw = (b - ZERO_BLKS - SPLIT_BLKS) * 8 + (tid >> 5);
        int lane = tid & 31;
        if (gw < HIDDEN) {
            int j = gw;
            float w0 = W2[j * HIDDEN + lane];
            float w1 = W2[j * HIDDEN + lane + 32];
            float w2 = W2[j * HIDDEN + lane + 64];
            float w3 = W2[j * HIDDEN + lane + 96];
#pragma unroll
            for (int c = 0; c < N_CLASSES; c++) {
                float v = w0 * Wl[lane * N_CLASSES + c]
                        + w1 * Wl[(lane + 32) * N_CLASSES + c]
                        + w2 * Wl[(lane + 64) * N_CLASSES + c]
                        + w3 * Wl[(lane + 96) * N_CLASSES + c];
#pragma unroll
                for (int s = 16; s > 0; s >>= 1)
                    v += __shfl_down_sync(0xffffffffu, v, s);
                if (lane == 0) g_Wc[j * N_CLASSES + c] = v;
            }
        } else if (gw < HIDDEN + N_CLASSES) {
            int c = gw - HIDDEN;
            float v = b2[lane]      * Wl[lane * N_CLASSES + c]
                    + b2[lane + 32] * Wl[(lane + 32) * N_CLASSES + c]
                    + b2[lane + 64] * Wl[(lane + 64) * N_CLASSES + c]
                    + b2[lane + 96] * Wl[(lane + 96) * N_CLASSES + c];
#pragma unroll
            for (int s = 16; s > 0; s >>= 1)
                v += __shfl_down_sync(0xffffffffu, v, s);
            if (lane == 0) g_bc[c] = v + bl[c];
        }
    }
}

// ---------------- ELL adjacency build: single pass, no scan ----------------
__global__ void fill_ell_k(const int* __restrict__ ei) {
    int e = blockIdx.x * blockDim.x + threadIdx.x;
    if (e < N_EDGES) {
        int s = clamp_node(ei[e]);
        int d = clamp_node(ei[N_EDGES + e]);
        int slot = atomicAdd(&g_deg[d], 1);
        if (slot < ELL_CAP) g_ell[d * ELL_CAP + slot] = s;
    }
}

// ---------------- edge aggregation: warp per node ----------------
__global__ void agg_k(int insel, const float* __restrict__ x) {
    int w    = (blockIdx.x * blockDim.x + threadIdx.x) >> 5;
    int lane = threadIdx.x & 31;
    if (w >= N_NODES) return;
    const float* feat = pick_feat(insel, x);
    int deg = g_deg[w];
    if (deg > ELL_CAP) deg = ELL_CAP;
    const int* row = &g_ell[w * ELL_CAP];
    const float4* f4 = (const float4*)feat;
    float4 acc = f4[w * 32 + lane];   // self feature
    int j = 0;
    for (; j + 1 < deg; j += 2) {
        int s0 = row[j], s1 = row[j + 1];
        float4 v0 = f4[s0 * 32 + lane];
        float4 v1 = f4[s1 * 32 + lane];
        acc.x += v0.x + v1.x; acc.y += v0.y + v1.y;
        acc.z += v0.z + v1.z; acc.w += v0.w + v1.w;
    }
    if (j < deg) {
        float4 v = f4[row[j] * 32 + lane];
        acc.x += v.x; acc.y += v.y; acc.z += v.z; acc.w += v.w;
    }
    ((float4*)g_agg)[w * 32 + lane] = acc;
}

// ---------------- tensor-core fused 2-layer MLP (3xBF16 split + ldmatrix) ----------
// block: 128 nodes x 128 cols, 256 threads (8 warps = 4m x 2n, warp tile 32x64)
// 2 CTAs/SM: smem = INPh/l 128x136 bf16 (69632) + WHT/WLT 128x72 bf16 (36864) = 106496
#define M_TILE 128
#define INP_S 136   // bf16 stride: row stride 272B -> ldmatrix conflict-free
#define WT_S  72    // bf16 stride: row stride 144B -> ldmatrix conflict-free
#define OUT_S 132   // f32 stride for epilogue staging

#define MMA_BF16(C, A0, A1, A2, A3, B0, B1)                                 \
    asm volatile(                                                           \
        "mma.sync.aligned.m16n8k16.row.col.f32.bf16.bf16.f32 "              \
        "{%0,%1,%2,%3}, {%4,%5,%6,%7}, {%8,%9}, {%0,%1,%2,%3};"             \
        : "+f"(C[0]), "+f"(C[1]), "+f"(C[2]), "+f"(C[3])                    \
        : "r"(A0), "r"(A1), "r"(A2), "r"(A3), "r"(B0), "r"(B1))

#define LDSM_X4(R0, R1, R2, R3, ADDR)                                       \
    asm volatile("ldmatrix.sync.aligned.m8n8.x4.shared.b16 {%0,%1,%2,%3}, [%4];" \
        : "=r"(R0), "=r"(R1), "=r"(R2), "=r"(R3) : "r"(ADDR))

__device__ __forceinline__ uint32_t pack_bf16x2(float a, float b) {
    __nv_bfloat162 t = __floats2bfloat162_rn(a, b);
    return *(uint32_t*)&t;
}

// one k16 step: A via 4 ldmatrix.x4 (2 m-frags x hi/lo), B via 8 ldmatrix.x4, 48 MMAs
__device__ __forceinline__ void mma_kstep_ldsm(
        uint32_t aH, uint32_t aL,          // per-thread A base addrs (mt=0)
        uint32_t bH, uint32_t bL,          // per-thread B base addrs (g=0)
        int kk, int kb, float acc[2][8][4]) {
    const uint32_t MT_OFF = 16 * INP_S * 2;
    uint32_t ah[2][4], al[2][4];
#pragma unroll
    for (int mt = 0; mt < 2; mt++) {
        LDSM_X4(ah[mt][0], ah[mt][1], ah[mt][2], ah[mt][3], aH + mt * MT_OFF + kk * 2);
        LDSM_X4(al[mt][0], al[mt][1], al[mt][2], al[mt][3], aL + mt * MT_OFF + kk * 2);
    }
#pragma unroll
    for (int g = 0; g < 4; g++) {
        uint32_t boff = g * (16 * WT_S * 2) + kb * 2;
        uint32_t bh0, bh1, bh2, bh3, bl0, bl1, bl2, bl3;
        LDSM_X4(bh0, bh1, bh2, bh3, bH + boff);
        LDSM_X4(bl0, bl1, bl2, bl3, bL + boff);
#pragma unroll
        for (int mt = 0; mt < 2; mt++) {
            MMA_BF16(acc[mt][2 * g],     ah[mt][0], ah[mt][1], ah[mt][2], ah[mt][3], bh0, bh1);
            MMA_BF16(acc[mt][2 * g],     al[mt][0], al[mt][1], al[mt][2], al[mt][3], bh0, bh1);
            MMA_BF16(acc[mt][2 * g],     ah[mt][0], ah[mt][1], ah[mt][2], ah[mt][3], bl0, bl1);
            MMA_BF16(acc[mt][2 * g + 1], ah[mt][0], ah[mt][1], ah[mt][2], ah[mt][3], bh2, bh3);
            MMA_BF16(acc[mt][2 * g + 1], al[mt][0], al[mt][1], al[mt][2], al[mt][3], bh2, bh3);
            MMA_BF16(acc[mt][2 * g + 1], ah[mt][0], ah[mt][1], ah[mt][2], ah[mt][3], bl2, bl3);
        }
    }
}

// skip2 == 0: out = relu?((relu(INP@W1+b1))@W2+b2)
// skip2 == 1: out = relu(INP@W1+b1)           (GEMM2 folded into classifier)
__global__ void __launch_bounds__(256, 2) mlp_tc_k(
        const float* __restrict__ b1, const float* __restrict__ b2,
        int outsel, int do_relu, int skip2) {
    extern __shared__ char smraw[];
    __nv_bfloat16* INPh = (__nv_bfloat16*)smraw;                 // 128*136*2 = 34816
    __nv_bfloat16* INPl = INPh + M_TILE * INP_S;                 // 34816
    __nv_bfloat16* WHT  = INPl + M_TILE * INP_S;                 // 128*72*2 = 18432
    __nv_bfloat16* WLT  = WHT + 128 * WT_S;                      // 18432
    float* FOUT = (float*)smraw;  // aliases INPh+INPl (67584 <= 69632)

    float* out = pick_out(outsel);

    int tid = threadIdx.x;
    int lane = tid & 31, warp = tid >> 5;
    int base = blockIdx.x * M_TILE;
    const int wm = (warp >> 1) * 32;   // 0,32,64,96
    const int wn = (warp & 1) * 64;    // 0,64

    // per-thread ldmatrix row addresses
    // A x4 quadrants: m0=(r,k) m1=(r+8,k) m2=(r,k+8) m3=(r+8,k+8)
    int a_row = wm + (lane & 7) + ((lane >> 3) & 1) * 8;
    int a_k   = (lane >> 4) * 8;
    uint32_t INPh_u = smem_u32(INPh), INPl_u = smem_u32(INPl);
    uint32_t WHT_u  = smem_u32(WHT),  WLT_u  = smem_u32(WLT);
    uint32_t aH = INPh_u + (a_row * INP_S + a_k) * 2;
    uint32_t aL = INPl_u + (a_row * INP_S + a_k) * 2;
    // B x4 quadrants (group g): m0=(n2g,k) m1=(n2g,k+8) m2=(n2g+1,k) m3=(n2g+1,k+8)
    int b_row = wn + (lane & 7) + ((lane >> 4) & 1) * 8;
    int b_k   = ((lane >> 3) & 1) * 8;
    uint32_t bH = WHT_u + (b_row * WT_S + b_k) * 2;
    uint32_t bL = WLT_u + (b_row * WT_S + b_k) * 2;

    // load INP = g_agg, split into bf16 hi/lo (zero-pad tail rows)
    for (int i = tid; i < M_TILE * 32; i += 256) {
        int row = i >> 5, c4 = i & 31;
        int node = base + row;
        float4 v = make_float4(0.f, 0.f, 0.f, 0.f);
        if (node < N_NODES)
            v = ((const float4*)g_agg)[node * 32 + c4];
        float hx = __bfloat162float(__float2bfloat16_rn(v.x));
        float hy = __bfloat162float(__float2bfloat16_rn(v.y));
        float hz = __bfloat162float(__float2bfloat16_rn(v.z));
        float hw = __bfloat162float(__float2bfloat16_rn(v.w));
        *(uint2*)&INPh[row * INP_S + c4 * 4] =
            make_uint2(pack_bf16x2(v.x, v.y), pack_bf16x2(v.z, v.w));
        *(uint2*)&INPl[row * INP_S + c4 * 4] =
            make_uint2(pack_bf16x2(v.x - hx, v.y - hy), pack_bf16x2(v.z - hz, v.w - hw));
    }

    float acc[2][8][4];
#pragma unroll
    for (int mt = 0; mt < 2; mt++)
#pragma unroll
        for (int nt = 0; nt < 8; nt++)
#pragma unroll
            for (int r = 0; r < 4; r++) acc[mt][nt][r] = 0.f;

    // ---- GEMM 1: INP @ W1 (2 k-chunks of 64) ----
    for (int kc = 0; kc < 2; kc++) {
        __syncthreads();
        for (int i = tid; i < 128 * 8; i += 256) {   // 8 uint4 per n-row (64 bf16)
            int n = i >> 3, q = i & 7;
            *(uint4*)&WHT[n * WT_S + q * 8] =
                *(const uint4*)&g_W1hT[n * HIDDEN + kc * 64 + q * 8];
            *(uint4*)&WLT[n * WT_S + q * 8] =
                *(const uint4*)&g_W1lT[n * HIDDEN + kc * 64 + q * 8];
        }
        __syncthreads();
#pragma unroll
        for (int ks = 0; ks < 4; ks++)
            mma_kstep_ldsm(aH, aL, bH, bL, kc * 64 + ks * 16, ks * 16, acc);
    }
    __syncthreads();  // all INP reads done

    if (skip2) {
        // out = relu(acc + b1) directly (FOUT aliases INP, safe after sync)
#pragma unroll
        for (int mt = 0; mt < 2; mt++) {
            int row = wm + mt * 16 + (lane >> 2);
#pragma unroll
            for (int nt = 0; nt < 8; nt++) {
                int col = wn + nt * 8 + 2 * (lane & 3);
                float2 bb = *(const float2*)(b1 + col);
                float2 v0, v1;
                v0.x = fmaxf(acc[mt][nt][0] + bb.x, 0.f);
                v0.y = fmaxf(acc[mt][nt][1] + bb.y, 0.f);
                v1.x = fmaxf(acc[mt][nt][2] + bb.x, 0.f);
                v1.y = fmaxf(acc[mt][nt][3] + bb.y, 0.f);
                *(float2*)&FOUT[row * OUT_S + col] = v0;
                *(float2*)&FOUT[(row + 8) * OUT_S + col] = v1;
            }
        }
        __syncthreads();
        for (int i = tid; i < M_TILE * 32; i += 256) {
            int row2 = i >> 5, c4 = i & 31;
            int node = base + row2;
            if (node < N_NODES)
                ((float4*)out)[node * 32 + c4] = *(float4*)&FOUT[row2 * OUT_S + c4 * 4];
        }
        return;
    }

    // MID = relu(acc + b1) -> split bf16, overwrite INPh/INPl
#pragma unroll
    for (int mt = 0; mt < 2; mt++) {
        int row = wm + mt * 16 + (lane >> 2);
#pragma unroll
        for (int nt = 0; nt < 8; nt++) {
            int col = wn + nt * 8 + 2 * (lane & 3);
            float2 bb = *(const float2*)(b1 + col);
            float m0 = fmaxf(acc[mt][nt][0] + bb.x, 0.f);
            float m1 = fmaxf(acc[mt][nt][1] + bb.y, 0.f);
            float m2 = fmaxf(acc[mt][nt][2] + bb.x, 0.f);
            float m3 = fmaxf(acc[mt][nt][3] + bb.y, 0.f);
            float h0 = __bfloat162float(__float2bfloat16_rn(m0));
            float h1 = __bfloat162float(__float2bfloat16_rn(m1));
            float h2 = __bfloat162float(__float2bfloat16_rn(m2));
            float h3 = __bfloat162float(__float2bfloat16_rn(m3));
            *(uint32_t*)&INPh[row * INP_S + col]       = pack_bf16x2(m0, m1);
            *(uint32_t*)&INPl[row * INP_S + col]       = pack_bf16x2(m0 - h0, m1 - h1);
            *(uint32_t*)&INPh[(row + 8) * INP_S + col] = pack_bf16x2(m2, m3);
            *(uint32_t*)&INPl[(row + 8) * INP_S + col] = pack_bf16x2(m2 - h2, m3 - h3);
        }
    }

#pragma unroll
    for (int mt = 0; mt < 2; mt++)
#pragma unroll
        for (int nt = 0; nt < 8; nt++)
#pragma unroll
            for (int r = 0; r < 4; r++) acc[mt][nt][r] = 0.f;

    // ---- GEMM 2: MID @ W2 ----
    for (int kc = 0; kc < 2; kc++) {
        __syncthreads();  // MID writes visible / prev chunk reads done
        for (int i = tid; i < 128 * 8; i += 256) {
            int n = i >> 3, q = i & 7;
            *(uint4*)&WHT[n * WT_S + q * 8] =
                *(const uint4*)&g_W2hT[n * HIDDEN + kc * 64 + q * 8];
            *(uint4*)&WLT[n * WT_S + q * 8] =
                *(const uint4*)&g_W2lT[n * HIDDEN + kc * 64 + q * 8];
        }
        __syncthreads();
#pragma unroll
        for (int ks = 0; ks < 4; ks++)
            mma_kstep_ldsm(aH, aL, bH, bL, kc * 64 + ks * 16, ks * 16, acc);
    }
    __syncthreads();  // all MID reads done -> FOUT may alias INP

    // OUT = (acc + b2) [relu?] -> f32 staging, then coalesced copy out
#pragma unroll
    for (int mt = 0; mt < 2; mt++) {
        int row = wm + mt * 16 + (lane >> 2);
#pragma unroll
        for (int nt = 0; nt < 8; nt++) {
            int col = wn + nt * 8 + 2 * (lane & 3);
            float2 bb = *(const float2*)(b2 + col);
            float2 v0, v1;
            v0.x = acc[mt][nt][0] + bb.x;
            v0.y = acc[mt][nt][1] + bb.y;
            v1.x = acc[mt][nt][2] + bb.x;
            v1.y = acc[mt][nt][3] + bb.y;
            if (do_relu) {
                v0.x = fmaxf(v0.x, 0.f); v0.y = fmaxf(v0.y, 0.f);
                v1.x = fmaxf(v1.x, 0.f); v1.y = fmaxf(v1.y, 0.f);
            }
            *(float2*)&FOUT[row * OUT_S + col] = v0;
            *(float2*)&FOUT[(row + 8) * OUT_S + col] = v1;
        }
    }
    __syncthreads();

    for (int i = tid; i < M_TILE * 32; i += 256) {
        int row = i >> 5, c4 = i & 31;
        int node = base + row;
        if (node < N_NODES)
            ((float4*)out)[node * 32 + c4] = *(float4*)&FOUT[row * OUT_S + c4 * 4];
    }
}

// ---------------- mean pool per graph (batch is sorted, int32) ----------------
__device__ __forceinline__ int lb_batch(const int* b, int v) {
    int lo = 0, hi = N_NODES;
    while (lo < hi) {
        int m = (lo + hi) >> 1;
        if (b[m] < v) lo = m + 1; else hi = m;
    }
    return lo;
}

__global__ void pool_k(const int* __restrict__ batch) {
    int g = blockIdx.x;
    int t = threadIdx.x;
    int lo = lb_batch(batch, g);
    int hi = lb_batch(batch, g + 1);
    float s = 0.f;
    for (int n = lo; n < hi; n++) s += g_f1[n * HIDDEN + t];
    int cnt = hi - lo;
    float c = (float)(cnt > 0 ? cnt : 1);
    g_pooled[g * HIDDEN + t] = s / c;
}

// ---------------- final classifier: pooled @ Wc + bc ----------------
__global__ void final_k(float* __restrict__ out) {
    int i = blockIdx.x * blockDim.x + threadIdx.x;
    if (i < N_GRAPHS * N_CLASSES) {
        int g = i / N_CLASSES, c = i % N_CLASSES;
        float s = g_bc[c];
        const float* p = &g_pooled[g * HIDDEN];
        for (int k = 0; k < HIDDEN; k++) s += p[k] * g_Wc[k * N_CLASSES + c];
        out[i] = s;
    }
}

// ---------------- launcher ----------------
extern "C" void kernel_launch(void* const* d_in, const int* in_sizes, int n_in,
                              void* d_out, int out_size) {
    const float* x     = (const float*)d_in[0];
    const int*   ei    = (const int*)d_in[1];
    const int*   batch = (const int*)d_in[2];
    const float* W1    = (const float*)d_in[3];
    const float* b1    = (const float*)d_in[4];
    const float* W2    = (const float*)d_in[5];
    const float* b2    = (const float*)d_in[6];
    const float* Wl    = (const float*)d_in[7];
    const float* bl    = (const float*)d_in[8];
    float* out = (float*)d_out;

    const int MLP_SMEM = (2 * M_TILE * INP_S + 2 * 128 * WT_S) * 2;  // 106496 B
    cudaFuncSetAttribute(mlp_tc_k, cudaFuncAttributeMaxDynamicSharedMemorySize, MLP_SMEM);

    // prep: zero+split+fold, then single-pass ELL build (no scan, no hist)
    prep1_k<<<ZERO_BLKS + SPLIT_BLKS + 18, 256>>>(W1, W2, b2, Wl, bl);
    fill_ell_k<<<(N_EDGES + 255) / 256, 256>>>(ei);

    const int AGG_BLOCKS = (N_NODES * 32 + 255) / 256;
    const int MLP_BLOCKS = (N_NODES + M_TILE - 1) / M_TILE;   // 391

    // layer 0: x -> g_f1 (relu)
    agg_k<<<AGG_BLOCKS, 256>>>(0, x);
    mlp_tc_k<<<MLP_BLOCKS, 256, MLP_SMEM>>>(b1, b2, 1, 1, 0);
    // layer 1: g_f1 -> g_f2 (relu)
    agg_k<<<AGG_BLOCKS, 256>>>(1, x);
    mlp_tc_k<<<MLP_BLOCKS, 256, MLP_SMEM>>>(b1, b2, 2, 1, 0);
    // layer 2: g_f2 -> g_f1 = MID only (GEMM2 folded into classifier)
    agg_k<<<AGG_BLOCKS, 256>>>(2, x);
    mlp_tc_k<<<MLP_BLOCKS, 256, MLP_SMEM>>>(b1, b2, 1, 0, 1);

    pool_k<<<N_GRAPHS, HIDDEN>>>(batch);
    final_k<<<(N_GRAPHS * N_CLASSES + 255) / 256, 256>>>(out);
}

// round 15
// speedup vs baseline: 1.6016x; 1.6016x over previous
#include <cuda_runtime.h>
#include <cuda_bf16.h>
#include <cstdint>

#define N_NODES  50000
#define N_EDGES  800000
#define HIDDEN   128
#define N_GRAPHS 256
#define N_CLASSES 10
#define ELL_CAP  96   // max in-degree capacity; P(deg>=96) ~ 1e-40 for Poisson(16)

// -------- device scratch (no allocations allowed) --------
__device__ __align__(16) float g_agg[N_NODES * HIDDEN];
__device__ __align__(16) float g_f1[N_NODES * HIDDEN];
__device__ __align__(16) float g_f2[N_NODES * HIDDEN];
__device__ int   g_deg[N_NODES];
__device__ int   g_ell[N_NODES * ELL_CAP];
__device__ __align__(16) float g_pooled[N_GRAPHS * HIDDEN];
// folded classifier: Wc = W2 @ Wl (128x10), bc = b2 @ Wl + bl (10)
__device__ __align__(16) float g_Wc[HIDDEN * N_CLASSES];
__device__ float g_bc[N_CLASSES];
// bf16 hi/lo split weights, TRANSPOSED to [n][k] (built once per call)
__device__ __align__(16) __nv_bfloat16 g_W1hT[HIDDEN * HIDDEN];
__device__ __align__(16) __nv_bfloat16 g_W1lT[HIDDEN * HIDDEN];
__device__ __align__(16) __nv_bfloat16 g_W2hT[HIDDEN * HIDDEN];
__device__ __align__(16) __nv_bfloat16 g_W2lT[HIDDEN * HIDDEN];

__device__ __forceinline__ const float* pick_feat(int sel, const float* x) {
    return sel == 0 ? x : (sel == 1 ? g_f1 : g_f2);
}
__device__ __forceinline__ float* pick_out(int sel) {
    return sel == 1 ? g_f1 : g_f2;
}
__device__ __forceinline__ int clamp_node(int v) {
    v = v < 0 ? 0 : v;
    return v >= N_NODES ? N_NODES - 1 : v;
}
__device__ __forceinline__ uint32_t smem_u32(const void* p) {
    uint32_t a;
    asm("{ .reg .u64 t; cvta.to.shared.u64 t, %1; cvt.u32.u64 %0, t; }" : "=r"(a) : "l"(p));
    return a;
}

// ---------------- merged prep: zero_deg + split_w + fold_wc ----------------
#define ZERO_BLKS 196
#define SPLIT_BLKS 64
__global__ void prep1_k(const float* __restrict__ W1, const float* __restrict__ W2,
                        const float* __restrict__ b2, const float* __restrict__ Wl,
                        const float* __restrict__ bl) {
    int b = blockIdx.x;
    int tid = threadIdx.x;
    if (b < ZERO_BLKS) {
        int i = b * 256 + tid;
        if (i < N_NODES) g_deg[i] = 0;
    } else if (b < ZERO_BLKS + SPLIT_BLKS) {
        int i = (b - ZERO_BLKS) * 256 + tid;   // i = n*128 + k
        int n = i >> 7, k = i & 127;
        float w = W1[k * HIDDEN + n];
        __nv_bfloat16 h = __float2bfloat16_rn(w);
        g_W1hT[i] = h;
        g_W1lT[i] = __float2bfloat16_rn(w - __bfloat162float(h));
        w = W2[k * HIDDEN + n];
        h = __float2bfloat16_rn(w);
        g_W2hT[i] = h;
        g_W2lT[i] = __float2bfloat16_rn(w - __bfloat162float(h));
    } else {
        int gw = (b - ZERO_BLKS - SPLIT_BLKS) * 8 + (tid >> 5);
        int lane = tid & 31;
        if (gw < HIDDEN) {
            int j = gw;
            float w0 = W2[j * HIDDEN + lane];
            float w1 = W2[j * HIDDEN + lane + 32];
            float w2 = W2[j * HIDDEN + lane + 64];
            float w3 = W2[j * HIDDEN + lane + 96];
#pragma unroll
            for (int c = 0; c < N_CLASSES; c++) {
                float v = w0 * Wl[lane * N_CLASSES + c]
                        + w1 * Wl[(lane + 32) * N_CLASSES + c]
                        + w2 * Wl[(lane + 64) * N_CLASSES + c]
                        + w3 * Wl[(lane + 96) * N_CLASSES + c];
#pragma unroll
                for (int s = 16; s > 0; s >>= 1)
                    v += __shfl_down_sync(0xffffffffu, v, s);
                if (lane == 0) g_Wc[j * N_CLASSES + c] = v;
            }
        } else if (gw < HIDDEN + N_CLASSES) {
            int c = gw - HIDDEN;
            float v = b2[lane]      * Wl[lane * N_CLASSES + c]
                    + b2[lane + 32] * Wl[(lane + 32) * N_CLASSES + c]
                    + b2[lane + 64] * Wl[(lane + 64) * N_CLASSES + c]
                    + b2[lane + 96] * Wl[(lane + 96) * N_CLASSES + c];
#pragma unroll
            for (int s = 16; s > 0; s >>= 1)
                v += __shfl_down_sync(0xffffffffu, v, s);
            if (lane == 0) g_bc[c] = v + bl[c];
        }
    }
}

// ---------------- ELL adjacency build: single pass, no scan ----------------
__global__ void fill_ell_k(const int* __restrict__ ei) {
    int e = blockIdx.x * blockDim.x + threadIdx.x;
    if (e < N_EDGES) {
        int s = clamp_node(ei[e]);
        int d = clamp_node(ei[N_EDGES + e]);
        int slot = atomicAdd(&g_deg[d], 1);
        if (slot < ELL_CAP) g_ell[d * ELL_CAP + slot] = s;
    }
}

// ---------------- edge aggregation: warp per node ----------------
__global__ void agg_k(int insel, const float* __restrict__ x) {
    int w    = (blockIdx.x * blockDim.x + threadIdx.x) >> 5;
    int lane = threadIdx.x & 31;
    if (w >= N_NODES) return;
    const float* feat = pick_feat(insel, x);
    int deg = g_deg[w];
    if (deg > ELL_CAP) deg = ELL_CAP;
    const int* row = &g_ell[w * ELL_CAP];
    const float4* f4 = (const float4*)feat;
    float4 acc = f4[w * 32 + lane];   // self feature
    int j = 0;
    for (; j + 1 < deg; j += 2) {
        int s0 = row[j], s1 = row[j + 1];
        float4 v0 = f4[s0 * 32 + lane];
        float4 v1 = f4[s1 * 32 + lane];
        acc.x += v0.x + v1.x; acc.y += v0.y + v1.y;
        acc.z += v0.z + v1.z; acc.w += v0.w + v1.w;
    }
    if (j < deg) {
        float4 v = f4[row[j] * 32 + lane];
        acc.x += v.x; acc.y += v.y; acc.z += v.z; acc.w += v.w;
    }
    ((float4*)g_agg)[w * 32 + lane] = acc;
}

// ---------------- tensor-core fused 2-layer MLP (3xBF16 split + ldmatrix) ----------
// block: 64 nodes x 128 cols, 256 threads (8 warps = 2m x 4n, warp tile 32x32)
// 3 CTAs/SM: smem = INPh/l 64x136 bf16 (34816) + WHT/WLT 128x72 bf16 (36864) = 71680
#define M_TILE 64
#define INP_S 136   // bf16 stride: row stride 272B -> ldmatrix conflict-free
#define WT_S  72    // bf16 stride: row stride 144B -> ldmatrix conflict-free
#define OUT_S 132   // f32 stride for epilogue staging

#define MMA_BF16(C, A0, A1, A2, A3, B0, B1)                                 \
    asm volatile(                                                           \
        "mma.sync.aligned.m16n8k16.row.col.f32.bf16.bf16.f32 "              \
        "{%0,%1,%2,%3}, {%4,%5,%6,%7}, {%8,%9}, {%0,%1,%2,%3};"             \
        : "+f"(C[0]), "+f"(C[1]), "+f"(C[2]), "+f"(C[3])                    \
        : "r"(A0), "r"(A1), "r"(A2), "r"(A3), "r"(B0), "r"(B1))

#define LDSM_X4(R0, R1, R2, R3, ADDR)                                       \
    asm volatile("ldmatrix.sync.aligned.m8n8.x4.shared.b16 {%0,%1,%2,%3}, [%4];" \
        : "=r"(R0), "=r"(R1), "=r"(R2), "=r"(R3) : "r"(ADDR))

__device__ __forceinline__ uint32_t pack_bf16x2(float a, float b) {
    __nv_bfloat162 t = __floats2bfloat162_rn(a, b);
    return *(uint32_t*)&t;
}

// one k16 step: A 4 LDSM.x4 (2 m-frags x hi/lo), B 4 LDSM.x4 (2 n-groups x hi/lo), 24 MMA
__device__ __forceinline__ void mma_kstep_ldsm(
        uint32_t aH, uint32_t aL,          // per-thread A base addrs (mt=0)
        uint32_t bH, uint32_t bL,          // per-thread B base addrs (g=0)
        int kk, int kb, float acc[2][4][4]) {
    const uint32_t MT_OFF = 16 * INP_S * 2;
    uint32_t ah[2][4], al[2][4];
#pragma unroll
    for (int mt = 0; mt < 2; mt++) {
        LDSM_X4(ah[mt][0], ah[mt][1], ah[mt][2], ah[mt][3], aH + mt * MT_OFF + kk * 2);
        LDSM_X4(al[mt][0], al[mt][1], al[mt][2], al[mt][3], aL + mt * MT_OFF + kk * 2);
    }
#pragma unroll
    for (int g = 0; g < 2; g++) {
        uint32_t boff = g * (16 * WT_S * 2) + kb * 2;
        uint32_t bh0, bh1, bh2, bh3, bl0, bl1, bl2, bl3;
        LDSM_X4(bh0, bh1, bh2, bh3, bH + boff);
        LDSM_X4(bl0, bl1, bl2, bl3, bL + boff);
#pragma unroll
        for (int mt = 0; mt < 2; mt++) {
            MMA_BF16(acc[mt][2 * g],     ah[mt][0], ah[mt][1], ah[mt][2], ah[mt][3], bh0, bh1);
            MMA_BF16(acc[mt][2 * g],     al[mt][0], al[mt][1], al[mt][2], al[mt][3], bh0, bh1);
            MMA_BF16(acc[mt][2 * g],     ah[mt][0], ah[mt][1], ah[mt][2], ah[mt][3], bl0, bl1);
            MMA_BF16(acc[mt][2 * g + 1], ah[mt][0], ah[mt][1], ah[mt][2], ah[mt][3], bh2, bh3);
            MMA_BF16(acc[mt][2 * g + 1], al[mt][0], al[mt][1], al[mt][2], al[mt][3], bh2, bh3);
            MMA_BF16(acc[mt][2 * g + 1], ah[mt][0], ah[mt][1], ah[mt][2], ah[mt][3], bl2, bl3);
        }
    }
}

// skip2 == 0: out = relu?((relu(INP@W1+b1))@W2+b2)
// skip2 == 1: out = relu(INP@W1+b1)           (GEMM2 folded into classifier)
__global__ void __launch_bounds__(256, 3) mlp_tc_k(
        const float* __restrict__ b1, const float* __restrict__ b2,
        int outsel, int do_relu, int skip2) {
    extern __shared__ char smraw[];
    __nv_bfloat16* INPh = (__nv_bfloat16*)smraw;                 // 64*136*2 = 17408
    __nv_bfloat16* INPl = INPh + M_TILE * INP_S;                 // 17408
    __nv_bfloat16* WHT  = INPl + M_TILE * INP_S;                 // 128*72*2 = 18432
    __nv_bfloat16* WLT  = WHT + 128 * WT_S;                      // 18432
    float* FOUT = (float*)smraw;  // aliases INPh+INPl (33792 <= 34816)

    float* out = pick_out(outsel);

    int tid = threadIdx.x;
    int lane = tid & 31, warp = tid >> 5;
    int base = blockIdx.x * M_TILE;
    const int wm = (warp >> 2) * 32;   // 0,32
    const int wn = (warp & 3) * 32;    // 0,32,64,96

    // per-thread ldmatrix row addresses
    // A x4 quadrants: m0=(r,k) m1=(r+8,k) m2=(r,k+8) m3=(r+8,k+8)
    int a_row = wm + (lane & 7) + ((lane >> 3) & 1) * 8;
    int a_k   = (lane >> 4) * 8;
    uint32_t INPh_u = smem_u32(INPh), INPl_u = smem_u32(INPl);
    uint32_t WHT_u  = smem_u32(WHT),  WLT_u  = smem_u32(WLT);
    uint32_t aH = INPh_u + (a_row * INP_S + a_k) * 2;
    uint32_t aL = INPl_u + (a_row * INP_S + a_k) * 2;
    // B x4 quadrants (group g): m0=(n2g,k) m1=(n2g,k+8) m2=(n2g+1,k) m3=(n2g+1,k+8)
    int b_row = wn + (lane & 7) + ((lane >> 4) & 1) * 8;
    int b_k   = ((lane >> 3) & 1) * 8;
    uint32_t bH = WHT_u + (b_row * WT_S + b_k) * 2;
    uint32_t bL = WLT_u + (b_row * WT_S + b_k) * 2;

    // load INP = g_agg, split into bf16 hi/lo (zero-pad tail rows)
    for (int i = tid; i < M_TILE * 32; i += 256) {
        int row = i >> 5, c4 = i & 31;
        int node = base + row;
        float4 v = make_float4(0.f, 0.f, 0.f, 0.f);
        if (node < N_NODES)
            v = ((const float4*)g_agg)[node * 32 + c4];
        float hx = __bfloat162float(__float2bfloat16_rn(v.x));
        float hy = __bfloat162float(__float2bfloat16_rn(v.y));
        float hz = __bfloat162float(__float2bfloat16_rn(v.z));
        float hw = __bfloat162float(__float2bfloat16_rn(v.w));
        *(uint2*)&INPh[row * INP_S + c4 * 4] =
            make_uint2(pack_bf16x2(v.x, v.y), pack_bf16x2(v.z, v.w));
        *(uint2*)&INPl[row * INP_S + c4 * 4] =
            make_uint2(pack_bf16x2(v.x - hx, v.y - hy), pack_bf16x2(v.z - hz, v.w - hw));
    }

    float acc[2][4][4];
#pragma unroll
    for (int mt = 0; mt < 2; mt++)
#pragma unroll
        for (int nt = 0; nt < 4; nt++)
#pragma unroll
            for (int r = 0; r < 4; r++) acc[mt][nt][r] = 0.f;

    // ---- GEMM 1: INP @ W1 (2 k-chunks of 64) ----
    for (int kc = 0; kc < 2; kc++) {
        __syncthreads();
        for (int i = tid; i < 128 * 8; i += 256) {   // 8 uint4 per n-row (64 bf16)
            int n = i >> 3, q = i & 7;
            *(uint4*)&WHT[n * WT_S + q * 8] =
                *(const uint4*)&g_W1hT[n * HIDDEN + kc * 64 + q * 8];
            *(uint4*)&WLT[n * WT_S + q * 8] =
                *(const uint4*)&g_W1lT[n * HIDDEN + kc * 64 + q * 8];
        }
        __syncthreads();
#pragma unroll
        for (int ks = 0; ks < 4; ks++)
            mma_kstep_ldsm(aH, aL, bH, bL, kc * 64 + ks * 16, ks * 16, acc);
    }
    __syncthreads();  // all INP reads done

    if (skip2) {
        // out = relu(acc + b1) directly (FOUT aliases INP, safe after sync)
#pragma unroll
        for (int mt = 0; mt < 2; mt++) {
            int row = wm + mt * 16 + (lane >> 2);
#pragma unroll
            for (int nt = 0; nt < 4; nt++) {
                int col = wn + nt * 8 + 2 * (lane & 3);
                float2 bb = *(const float2*)(b1 + col);
                float2 v0, v1;
                v0.x = fmaxf(acc[mt][nt][0] + bb.x, 0.f);
                v0.y = fmaxf(acc[mt][nt][1] + bb.y, 0.f);
                v1.x = fmaxf(acc[mt][nt][2] + bb.x, 0.f);
                v1.y = fmaxf(acc[mt][nt][3] + bb.y, 0.f);
                *(float2*)&FOUT[row * OUT_S + col] = v0;
                *(float2*)&FOUT[(row + 8) * OUT_S + col] = v1;
            }
        }
        __syncthreads();
        for (int i = tid; i < M_TILE * 32; i += 256) {
            int row2 = i >> 5, c4 = i & 31;
            int node = base + row2;
            if (node < N_NODES)
                ((float4*)out)[node * 32 + c4] = *(float4*)&FOUT[row2 * OUT_S + c4 * 4];
        }
        return;
    }

    // MID = relu(acc + b1) -> split bf16, overwrite INPh/INPl
#pragma unroll
    for (int mt = 0; mt < 2; mt++) {
        int row = wm + mt * 16 + (lane >> 2);
#pragma unroll
        for (int nt = 0; nt < 4; nt++) {
            int col = wn + nt * 8 + 2 * (lane & 3);
            float2 bb = *(const float2*)(b1 + col);
            float m0 = fmaxf(acc[mt][nt][0] + bb.x, 0.f);
            float m1 = fmaxf(acc[mt][nt][1] + bb.y, 0.f);
            float m2 = fmaxf(acc[mt][nt][2] + bb.x, 0.f);
            float m3 = fmaxf(acc[mt][nt][3] + bb.y, 0.f);
            float h0 = __bfloat162float(__float2bfloat16_rn(m0));
            float h1 = __bfloat162float(__float2bfloat16_rn(m1));
            float h2 = __bfloat162float(__float2bfloat16_rn(m2));
            float h3 = __bfloat162float(__float2bfloat16_rn(m3));
            *(uint32_t*)&INPh[row * INP_S + col]       = pack_bf16x2(m0, m1);
            *(uint32_t*)&INPl[row * INP_S + col]       = pack_bf16x2(m0 - h0, m1 - h1);
            *(uint32_t*)&INPh[(row + 8) * INP_S + col] = pack_bf16x2(m2, m3);
            *(uint32_t*)&INPl[(row + 8) * INP_S + col] = pack_bf16x2(m2 - h2, m3 - h3);
        }
    }

#pragma unroll
    for (int mt = 0; mt < 2; mt++)
#pragma unroll
        for (int nt = 0; nt < 4; nt++)
#pragma unroll
            for (int r = 0; r < 4; r++) acc[mt][nt][r] = 0.f;

    // ---- GEMM 2: MID @ W2 ----
    for (int kc = 0; kc < 2; kc++) {
        __syncthreads();  // MID writes visible / prev chunk reads done
        for (int i = tid; i < 128 * 8; i += 256) {
            int n = i >> 3, q = i & 7;
            *(uint4*)&WHT[n * WT_S + q * 8] =
                *(const uint4*)&g_W2hT[n * HIDDEN + kc * 64 + q * 8];
            *(uint4*)&WLT[n * WT_S + q * 8] =
                *(const uint4*)&g_W2lT[n * HIDDEN + kc * 64 + q * 8];
        }
        __syncthreads();
#pragma unroll
        for (int ks = 0; ks < 4; ks++)
            mma_kstep_ldsm(aH, aL, bH, bL, kc * 64 + ks * 16, ks * 16, acc);
    }
    __syncthreads();  // all MID reads done -> FOUT may alias INP

    // OUT = (acc + b2) [relu?] -> f32 staging, then coalesced copy out
#pragma unroll
    for (int mt = 0; mt < 2; mt++) {
        int row = wm + mt * 16 + (lane >> 2);
#pragma unroll
        for (int nt = 0; nt < 4; nt++) {
            int col = wn + nt * 8 + 2 * (lane & 3);
            float2 bb = *(const float2*)(b2 + col);
            float2 v0, v1;
            v0.x = acc[mt][nt][0] + bb.x;
            v0.y = acc[mt][nt][1] + bb.y;
            v1.x = acc[mt][nt][2] + bb.x;
            v1.y = acc[mt][nt][3] + bb.y;
            if (do_relu) {
                v0.x = fmaxf(v0.x, 0.f); v0.y = fmaxf(v0.y, 0.f);
                v1.x = fmaxf(v1.x, 0.f); v1.y = fmaxf(v1.y, 0.f);
            }
            *(float2*)&FOUT[row * OUT_S + col] = v0;
            *(float2*)&FOUT[(row + 8) * OUT_S + col] = v1;
        }
    }
    __syncthreads();

    for (int i = tid; i < M_TILE * 32; i += 256) {
        int row = i >> 5, c4 = i & 31;
        int node = base + row;
        if (node < N_NODES)
            ((float4*)out)[node * 32 + c4] = *(float4*)&FOUT[row * OUT_S + c4 * 4];
    }
}

// ---------------- mean pool per graph (batch is sorted, int32) ----------------
__device__ __forceinline__ int lb_batch(const int* b, int v) {
    int lo = 0, hi = N_NODES;
    while (lo < hi) {
        int m = (lo + hi) >> 1;
        if (b[m] < v) lo = m + 1; else hi = m;
    }
    return lo;
}

__global__ void pool_k(const int* __restrict__ batch) {
    int g = blockIdx.x;
    int t = threadIdx.x;
    int lo = lb_batch(batch, g);
    int hi = lb_batch(batch, g + 1);
    float s = 0.f;
    for (int n = lo; n < hi; n++) s += g_f1[n * HIDDEN + t];
    int cnt = hi - lo;
    float c = (float)(cnt > 0 ? cnt : 1);
    g_pooled[g * HIDDEN + t] = s / c;
}

// ---------------- final classifier: pooled @ Wc + bc ----------------
__global__ void final_k(float* __restrict__ out) {
    int i = blockIdx.x * blockDim.x + threadIdx.x;
    if (i < N_GRAPHS * N_CLASSES) {
        int g = i / N_CLASSES, c = i % N_CLASSES;
        float s = g_bc[c];
        const float* p = &g_pooled[g * HIDDEN];
        for (int k = 0; k < HIDDEN; k++) s += p[k] * g_Wc[k * N_CLASSES + c];
        out[i] = s;
    }
}

// ---------------- launcher ----------------
extern "C" void kernel_launch(void* const* d_in, const int* in_sizes, int n_in,
                              void* d_out, int out_size) {
    const float* x     = (const float*)d_in[0];
    const int*   ei    = (const int*)d_in[1];
    const int*   batch = (const int*)d_in[2];
    const float* W1    = (const float*)d_in[3];
    const float* b1    = (const float*)d_in[4];
    const float* W2    = (const float*)d_in[5];
    const float* b2    = (const float*)d_in[6];
    const float* Wl    = (const float*)d_in[7];
    const float* bl    = (const float*)d_in[8];
    float* out = (float*)d_out;

    const int MLP_SMEM = (2 * M_TILE * INP_S + 2 * 128 * WT_S) * 2;  // 71680 B
    cudaFuncSetAttribute(mlp_tc_k, cudaFuncAttributeMaxDynamicSharedMemorySize, MLP_SMEM);

    // prep: zero+split+fold, then single-pass ELL build (no scan, no hist)
    prep1_k<<<ZERO_BLKS + SPLIT_BLKS + 18, 256>>>(W1, W2, b2, Wl, bl);
    fill_ell_k<<<(N_EDGES + 255) / 256, 256>>>(ei);

    const int AGG_BLOCKS = (N_NODES * 32 + 255) / 256;
    const int MLP_BLOCKS = (N_NODES + M_TILE - 1) / M_TILE;   // 782

    // layer 0: x -> g_f1 (relu)
    agg_k<<<AGG_BLOCKS, 256>>>(0, x);
    mlp_tc_k<<<MLP_BLOCKS, 256, MLP_SMEM>>>(b1, b2, 1, 1, 0);
    // layer 1: g_f1 -> g_f2 (relu)
    agg_k<<<AGG_BLOCKS, 256>>>(1, x);
    mlp_tc_k<<<MLP_BLOCKS, 256, MLP_SMEM>>>(b1, b2, 2, 1, 0);
    // layer 2: g_f2 -> g_f1 = MID only (GEMM2 folded into classifier)
    agg_k<<<AGG_BLOCKS, 256>>>(2, x);
    mlp_tc_k<<<MLP_BLOCKS, 256, MLP_SMEM>>>(b1, b2, 1, 0, 1);

    pool_k<<<N_GRAPHS, HIDDEN>>>(batch);
    final_k<<<(N_GRAPHS * N_CLASSES + 255) / 256, 256>>>(out);
}

// round 16
// speedup vs baseline: 1.6993x; 1.0610x over previous
#include <cuda_runtime.h>
#include <cuda_fp16.h>
#include <cstdint>

#define N_NODES  50000
#define N_EDGES  800000
#define HIDDEN   128
#define N_GRAPHS 256
#define N_CLASSES 10
#define ELL_CAP  96   // max in-degree capacity; P(deg>=96) ~ 1e-40 for Poisson(16)

// -------- device scratch (no allocations allowed) --------
__device__ __align__(16) float g_agg[N_NODES * HIDDEN];
__device__ __align__(16) float g_f1[N_NODES * HIDDEN];
__device__ __align__(16) float g_f2[N_NODES * HIDDEN];
__device__ int   g_deg[N_NODES];
__device__ int   g_ell[N_NODES * ELL_CAP];
__device__ __align__(16) float g_pooled[N_GRAPHS * HIDDEN];
// folded classifier: Wc = W2 @ Wl (128x10), bc = b2 @ Wl + bl (10)
__device__ __align__(16) float g_Wc[HIDDEN * N_CLASSES];
__device__ float g_bc[N_CLASSES];
// fp16 hi/residual split weights, TRANSPOSED to [n][k] (built once per call)
// W = Wh + Wl captures W to ~2^-22 relative (weights effectively exact)
__device__ __align__(16) __half g_W1hT[HIDDEN * HIDDEN];
__device__ __align__(16) __half g_W1lT[HIDDEN * HIDDEN];
__device__ __align__(16) __half g_W2hT[HIDDEN * HIDDEN];
__device__ __align__(16) __half g_W2lT[HIDDEN * HIDDEN];

__device__ __forceinline__ const float* pick_feat(int sel, const float* x) {
    return sel == 0 ? x : (sel == 1 ? g_f1 : g_f2);
}
__device__ __forceinline__ float* pick_out(int sel) {
    return sel == 1 ? g_f1 : g_f2;
}
__device__ __forceinline__ int clamp_node(int v) {
    v = v < 0 ? 0 : v;
    return v >= N_NODES ? N_NODES - 1 : v;
}
__device__ __forceinline__ uint32_t smem_u32(const void* p) {
    uint32_t a;
    asm("{ .reg .u64 t; cvta.to.shared.u64 t, %1; cvt.u32.u64 %0, t; }" : "=r"(a) : "l"(p));
    return a;
}

// ---------------- merged prep: zero_deg + split_w + fold_wc ----------------
#define ZERO_BLKS 196
#define SPLIT_BLKS 64
__global__ void prep1_k(const float* __restrict__ W1, const float* __restrict__ W2,
                        const float* __restrict__ b2, const float* __restrict__ Wl,
                        const float* __restrict__ bl) {
    int b = blockIdx.x;
    int tid = threadIdx.x;
    if (b < ZERO_BLKS) {
        int i = b * 256 + tid;
        if (i < N_NODES) g_deg[i] = 0;
    } else if (b < ZERO_BLKS + SPLIT_BLKS) {
        int i = (b - ZERO_BLKS) * 256 + tid;   // i = n*128 + k
        int n = i >> 7, k = i & 127;
        float w = W1[k * HIDDEN + n];
        __half h = __float2half_rn(w);
        g_W1hT[i] = h;
        g_W1lT[i] = __float2half_rn(w - __half2float(h));
        w = W2[k * HIDDEN + n];
        h = __float2half_rn(w);
        g_W2hT[i] = h;
        g_W2lT[i] = __float2half_rn(w - __half2float(h));
    } else {
        int gw = (b - ZERO_BLKS - SPLIT_BLKS) * 8 + (tid >> 5);
        int lane = tid & 31;
        if (gw < HIDDEN) {
            int j = gw;
            float w0 = W2[j * HIDDEN + lane];
            float w1 = W2[j * HIDDEN + lane + 32];
            float w2 = W2[j * HIDDEN + lane + 64];
            float w3 = W2[j * HIDDEN + lane + 96];
#pragma unroll
            for (int c = 0; c < N_CLASSES; c++) {
                float v = w0 * Wl[lane * N_CLASSES + c]
                        + w1 * Wl[(lane + 32) * N_CLASSES + c]
                        + w2 * Wl[(lane + 64) * N_CLASSES + c]
                        + w3 * Wl[(lane + 96) * N_CLASSES + c];
#pragma unroll
                for (int s = 16; s > 0; s >>= 1)
                    v += __shfl_down_sync(0xffffffffu, v, s);
                if (lane == 0) g_Wc[j * N_CLASSES + c] = v;
            }
        } else if (gw < HIDDEN + N_CLASSES) {
            int c = gw - HIDDEN;
            float v = b2[lane]      * Wl[lane * N_CLASSES + c]
                    + b2[lane + 32] * Wl[(lane + 32) * N_CLASSES + c]
                    + b2[lane + 64] * Wl[(lane + 64) * N_CLASSES + c]
                    + b2[lane + 96] * Wl[(lane + 96) * N_CLASSES + c];
#pragma unroll
            for (int s = 16; s > 0; s >>= 1)
                v += __shfl_down_sync(0xffffffffu, v, s);
            if (lane == 0) g_bc[c] = v + bl[c];
        }
    }
}

// ---------------- ELL adjacency build: single pass, no scan ----------------
__global__ void fill_ell_k(const int* __restrict__ ei) {
    int e = blockIdx.x * blockDim.x + threadIdx.x;
    if (e < N_EDGES) {
        int s = clamp_node(ei[e]);
        int d = clamp_node(ei[N_EDGES + e]);
        int slot = atomicAdd(&g_deg[d], 1);
        if (slot < ELL_CAP) g_ell[d * ELL_CAP + slot] = s;
    }
}

// ---------------- edge aggregation: warp per node ----------------
__global__ void agg_k(int insel, const float* __restrict__ x) {
    int w    = (blockIdx.x * blockDim.x + threadIdx.x) >> 5;
    int lane = threadIdx.x & 31;
    if (w >= N_NODES) return;
    const float* feat = pick_feat(insel, x);
    int deg = g_deg[w];
    if (deg > ELL_CAP) deg = ELL_CAP;
    const int* row = &g_ell[w * ELL_CAP];
    const float4* f4 = (const float4*)feat;
    float4 acc = f4[w * 32 + lane];   // self feature
    int j = 0;
    for (; j + 1 < deg; j += 2) {
        int s0 = row[j], s1 = row[j + 1];
        float4 v0 = f4[s0 * 32 + lane];
        float4 v1 = f4[s1 * 32 + lane];
        acc.x += v0.x + v1.x; acc.y += v0.y + v1.y;
        acc.z += v0.z + v1.z; acc.w += v0.w + v1.w;
    }
    if (j < deg) {
        float4 v = f4[row[j] * 32 + lane];
        acc.x += v.x; acc.y += v.y; acc.z += v.z; acc.w += v.w;
    }
    ((float4*)g_agg)[w * 32 + lane] = acc;
}

// ---------------- tensor-core fused 2-layer MLP (2xFP16 + ldmatrix) ----------------
// out ≈ x@(Wh+Wl): x rounded to fp16 once, W split exact to ~2^-22
// block: 64 nodes x 128 cols, 256 threads (8 warps = 2m x 4n, warp tile 32x32)
// 4 CTAs/SM: smem = INP 64x136 fp16 (17408) + WHT/WLT 128x72 fp16 (36864) = 54272
#define M_TILE 64
#define INP_S 136   // fp16 stride: row stride 272B -> ldmatrix conflict-free
#define WT_S  72    // fp16 stride: row stride 144B -> ldmatrix conflict-free
#define OUT_S 132   // f32 stride for epilogue staging

#define MMA_FP16(C, A0, A1, A2, A3, B0, B1)                                 \
    asm volatile(                                                           \
        "mma.sync.aligned.m16n8k16.row.col.f32.f16.f16.f32 "                \
        "{%0,%1,%2,%3}, {%4,%5,%6,%7}, {%8,%9}, {%0,%1,%2,%3};"             \
        : "+f"(C[0]), "+f"(C[1]), "+f"(C[2]), "+f"(C[3])                    \
        : "r"(A0), "r"(A1), "r"(A2), "r"(A3), "r"(B0), "r"(B1))

#define LDSM_X4(R0, R1, R2, R3, ADDR)                                       \
    asm volatile("ldmatrix.sync.aligned.m8n8.x4.shared.b16 {%0,%1,%2,%3}, [%4];" \
        : "=r"(R0), "=r"(R1), "=r"(R2), "=r"(R3) : "r"(ADDR))

__device__ __forceinline__ uint32_t pack_h2(float a, float b) {
    __half2 t = __floats2half2_rn(a, b);
    return *(uint32_t*)&t;
}

// one k16 step: A 2 LDSM.x4 (2 m-frags), B 4 LDSM.x4 (2 n-groups x Wh/Wl), 16 MMA
__device__ __forceinline__ void mma_kstep_ldsm(
        uint32_t aB,                       // per-thread A base addr (mt=0)
        uint32_t bH, uint32_t bL,          // per-thread B base addrs (g=0)
        int kk, int kb, float acc[2][4][4]) {
    const uint32_t MT_OFF = 16 * INP_S * 2;
    uint32_t a[2][4];
#pragma unroll
    for (int mt = 0; mt < 2; mt++)
        LDSM_X4(a[mt][0], a[mt][1], a[mt][2], a[mt][3], aB + mt * MT_OFF + kk * 2);
#pragma unroll
    for (int g = 0; g < 2; g++) {
        uint32_t boff = g * (16 * WT_S * 2) + kb * 2;
        uint32_t bh0, bh1, bh2, bh3, bl0, bl1, bl2, bl3;
        LDSM_X4(bh0, bh1, bh2, bh3, bH + boff);
        LDSM_X4(bl0, bl1, bl2, bl3, bL + boff);
#pragma unroll
        for (int mt = 0; mt < 2; mt++) {
            MMA_FP16(acc[mt][2 * g],     a[mt][0], a[mt][1], a[mt][2], a[mt][3], bh0, bh1);
            MMA_FP16(acc[mt][2 * g],     a[mt][0], a[mt][1], a[mt][2], a[mt][3], bl0, bl1);
            MMA_FP16(acc[mt][2 * g + 1], a[mt][0], a[mt][1], a[mt][2], a[mt][3], bh2, bh3);
            MMA_FP16(acc[mt][2 * g + 1], a[mt][0], a[mt][1], a[mt][2], a[mt][3], bl2, bl3);
        }
    }
}

// skip2 == 0: out = relu?((relu(INP@W1+b1))@W2+b2)
// skip2 == 1: out = relu(INP@W1+b1)           (GEMM2 folded into classifier)
__global__ void __launch_bounds__(256, 4) mlp_tc_k(
        const float* __restrict__ b1, const float* __restrict__ b2,
        int outsel, int do_relu, int skip2) {
    extern __shared__ char smraw[];
    __half* INP = (__half*)smraw;                    // 64*136*2 = 17408
    __half* WHT = INP + M_TILE * INP_S;              // 128*72*2 = 18432
    __half* WLT = WHT + 128 * WT_S;                  // 18432
    float* FOUT = (float*)smraw;  // overlays INP+WHT after final MMA (33792 <= 35840)

    float* out = pick_out(outsel);

    int tid = threadIdx.x;
    int lane = tid & 31, warp = tid >> 5;
    int base = blockIdx.x * M_TILE;
    const int wm = (warp >> 2) * 32;   // 0,32
    const int wn = (warp & 3) * 32;    // 0,32,64,96

    // per-thread ldmatrix row addresses
    // A x4 quadrants: m0=(r,k) m1=(r+8,k) m2=(r,k+8) m3=(r+8,k+8)
    int a_row = wm + (lane & 7) + ((lane >> 3) & 1) * 8;
    int a_k   = (lane >> 4) * 8;
    uint32_t INP_u = smem_u32(INP);
    uint32_t WHT_u = smem_u32(WHT), WLT_u = smem_u32(WLT);
    uint32_t aB = INP_u + (a_row * INP_S + a_k) * 2;
    // B x4 quadrants (group g): m0=(n2g,k) m1=(n2g,k+8) m2=(n2g+1,k) m3=(n2g+1,k+8)
    int b_row = wn + (lane & 7) + ((lane >> 4) & 1) * 8;
    int b_k   = ((lane >> 3) & 1) * 8;
    uint32_t bH = WHT_u + (b_row * WT_S + b_k) * 2;
    uint32_t bL = WLT_u + (b_row * WT_S + b_k) * 2;

    // load INP = fp16(g_agg) (zero-pad tail rows)
    for (int i = tid; i < M_TILE * 32; i += 256) {
        int row = i >> 5, c4 = i & 31;
        int node = base + row;
        float4 v = make_float4(0.f, 0.f, 0.f, 0.f);
        if (node < N_NODES)
            v = ((const float4*)g_agg)[node * 32 + c4];
        *(uint2*)&INP[row * INP_S + c4 * 4] =
            make_uint2(pack_h2(v.x, v.y), pack_h2(v.z, v.w));
    }

    float acc[2][4][4];
#pragma unroll
    for (int mt = 0; mt < 2; mt++)
#pragma unroll
        for (int nt = 0; nt < 4; nt++)
#pragma unroll
            for (int r = 0; r < 4; r++) acc[mt][nt][r] = 0.f;

    // ---- GEMM 1: INP @ W1 (2 k-chunks of 64) ----
    for (int kc = 0; kc < 2; kc++) {
        __syncthreads();
        for (int i = tid; i < 128 * 8; i += 256) {   // 8 uint4 per n-row (64 fp16)
            int n = i >> 3, q = i & 7;
            *(uint4*)&WHT[n * WT_S + q * 8] =
                *(const uint4*)&g_W1hT[n * HIDDEN + kc * 64 + q * 8];
            *(uint4*)&WLT[n * WT_S + q * 8] =
                *(const uint4*)&g_W1lT[n * HIDDEN + kc * 64 + q * 8];
        }
        __syncthreads();
#pragma unroll
        for (int ks = 0; ks < 4; ks++)
            mma_kstep_ldsm(aB, bH, bL, kc * 64 + ks * 16, ks * 16, acc);
    }
    __syncthreads();  // all INP reads done

    if (skip2) {
        // out = relu(acc + b1) directly (FOUT overlays INP/WHT, safe after sync)
#pragma unroll
        for (int mt = 0; mt < 2; mt++) {
            int row = wm + mt * 16 + (lane >> 2);
#pragma unroll
            for (int nt = 0; nt < 4; nt++) {
                int col = wn + nt * 8 + 2 * (lane & 3);
                float2 bb = *(const float2*)(b1 + col);
                float2 v0, v1;
                v0.x = fmaxf(acc[mt][nt][0] + bb.x, 0.f);
                v0.y = fmaxf(acc[mt][nt][1] + bb.y, 0.f);
                v1.x = fmaxf(acc[mt][nt][2] + bb.x, 0.f);
                v1.y = fmaxf(acc[mt][nt][3] + bb.y, 0.f);
                *(float2*)&FOUT[row * OUT_S + col] = v0;
                *(float2*)&FOUT[(row + 8) * OUT_S + col] = v1;
            }
        }
        __syncthreads();
        for (int i = tid; i < M_TILE * 32; i += 256) {
            int row2 = i >> 5, c4 = i & 31;
            int node = base + row2;
            if (node < N_NODES)
                ((float4*)out)[node * 32 + c4] = *(float4*)&FOUT[row2 * OUT_S + c4 * 4];
        }
        return;
    }

    // MID = fp16(relu(acc + b1)) -> overwrite INP
#pragma unroll
    for (int mt = 0; mt < 2; mt++) {
        int row = wm + mt * 16 + (lane >> 2);
#pragma unroll
        for (int nt = 0; nt < 4; nt++) {
            int col = wn + nt * 8 + 2 * (lane & 3);
            float2 bb = *(const float2*)(b1 + col);
            float m0 = fmaxf(acc[mt][nt][0] + bb.x, 0.f);
            float m1 = fmaxf(acc[mt][nt][1] + bb.y, 0.f);
            float m2 = fmaxf(acc[mt][nt][2] + bb.x, 0.f);
            float m3 = fmaxf(acc[mt][nt][3] + bb.y, 0.f);
            *(uint32_t*)&INP[row * INP_S + col]       = pack_h2(m0, m1);
            *(uint32_t*)&INP[(row + 8) * INP_S + col] = pack_h2(m2, m3);
        }
    }

#pragma unroll
    for (int mt = 0; mt < 2; mt++)
#pragma unroll
        for (int nt = 0; nt < 4; nt++)
#pragma unroll
            for (int r = 0; r < 4; r++) acc[mt][nt][r] = 0.f;

    // ---- GEMM 2: MID @ W2 ----
    for (int kc = 0; kc < 2; kc++) {
        __syncthreads();  // MID writes visible / prev chunk reads done
        for (int i = tid; i < 128 * 8; i += 256) {
            int n = i >> 3, q = i & 7;
            *(uint4*)&WHT[n * WT_S + q * 8] =
                *(const uint4*)&g_W2hT[n * HIDDEN + kc * 64 + q * 8];
            *(uint4*)&WLT[n * WT_S + q * 8] =
                *(const uint4*)&g_W2lT[n * HIDDEN + kc * 64 + q * 8];
        }
        __syncthreads();
#pragma unroll
        for (int ks = 0; ks < 4; ks++)
            mma_kstep_ldsm(aB, bH, bL, kc * 64 + ks * 16, ks * 16, acc);
    }
    __syncthreads();  // all MID reads done -> FOUT may overlay

    // OUT = (acc + b2) [relu?] -> f32 staging, then coalesced copy out
#pragma unroll
    for (int mt = 0; mt < 2; mt++) {
        int row = wm + mt * 16 + (lane >> 2);
#pragma unroll
        for (int nt = 0; nt < 4; nt++) {
            int col = wn + nt * 8 + 2 * (lane & 3);
            float2 bb = *(const float2*)(b2 + col);
            float2 v0, v1;
            v0.x = acc[mt][nt][0] + bb.x;
            v0.y = acc[mt][nt][1] + bb.y;
            v1.x = acc[mt][nt][2] + bb.x;
            v1.y = acc[mt][nt][3] + bb.y;
            if (do_relu) {
                v0.x = fmaxf(v0.x, 0.f); v0.y = fmaxf(v0.y, 0.f);
                v1.x = fmaxf(v1.x, 0.f); v1.y = fmaxf(v1.y, 0.f);
            }
            *(float2*)&FOUT[row * OUT_S + col] = v0;
            *(float2*)&FOUT[(row + 8) * OUT_S + col] = v1;
        }
    }
    __syncthreads();

    for (int i = tid; i < M_TILE * 32; i += 256) {
        int row = i >> 5, c4 = i & 31;
        int node = base + row;
        if (node < N_NODES)
            ((float4*)out)[node * 32 + c4] = *(float4*)&FOUT[row * OUT_S + c4 * 4];
    }
}

// ---------------- mean pool per graph (batch is sorted, int32) ----------------
__device__ __forceinline__ int lb_batch(const int* b, int v) {
    int lo = 0, hi = N_NODES;
    while (lo < hi) {
        int m = (lo + hi) >> 1;
        if (b[m] < v) lo = m + 1; else hi = m;
    }
    return lo;
}

__global__ void pool_k(const int* __restrict__ batch) {
    int g = blockIdx.x;
    int t = threadIdx.x;
    int lo = lb_batch(batch, g);
    int hi = lb_batch(batch, g + 1);
    float s = 0.f;
    for (int n = lo; n < hi; n++) s += g_f1[n * HIDDEN + t];
    int cnt = hi - lo;
    float c = (float)(cnt > 0 ? cnt : 1);
    g_pooled[g * HIDDEN + t] = s / c;
}

// ---------------- final classifier: pooled @ Wc + bc ----------------
__global__ void final_k(float* __restrict__ out) {
    int i = blockIdx.x * blockDim.x + threadIdx.x;
    if (i < N_GRAPHS * N_CLASSES) {
        int g = i / N_CLASSES, c = i % N_CLASSES;
        float s = g_bc[c];
        const float* p = &g_pooled[g * HIDDEN];
        for (int k = 0; k < HIDDEN; k++) s += p[k] * g_Wc[k * N_CLASSES + c];
        out[i] = s;
    }
}

// ---------------- launcher ----------------
extern "C" void kernel_launch(void* const* d_in, const int* in_sizes, int n_in,
                              void* d_out, int out_size) {
    const float* x     = (const float*)d_in[0];
    const int*   ei    = (const int*)d_in[1];
    const int*   batch = (const int*)d_in[2];
    const float* W1    = (const float*)d_in[3];
    const float* b1    = (const float*)d_in[4];
    const float* W2    = (const float*)d_in[5];
    const float* b2    = (const float*)d_in[6];
    const float* Wl    = (const float*)d_in[7];
    const float* bl    = (const float*)d_in[8];
    float* out = (float*)d_out;

    const int MLP_SMEM = (M_TILE * INP_S + 2 * 128 * WT_S) * 2;  // 54272 B
    cudaFuncSetAttribute(mlp_tc_k, cudaFuncAttributeMaxDynamicSharedMemorySize, MLP_SMEM);

    // prep: zero+split+fold, then single-pass ELL build (no scan, no hist)
    prep1_k<<<ZERO_BLKS + SPLIT_BLKS + 18, 256>>>(W1, W2, b2, Wl, bl);
    fill_ell_k<<<(N_EDGES + 255) / 256, 256>>>(ei);

    const int AGG_BLOCKS = (N_NODES * 32 + 255) / 256;
    const int MLP_BLOCKS = (N_NODES + M_TILE - 1) / M_TILE;   // 782

    // layer 0: x -> g_f1 (relu)
    agg_k<<<AGG_BLOCKS, 256>>>(0, x);
    mlp_tc_k<<<MLP_BLOCKS, 256, MLP_SMEM>>>(b1, b2, 1, 1, 0);
    // layer 1: g_f1 -> g_f2 (relu)
    agg_k<<<AGG_BLOCKS, 256>>>(1, x);
    mlp_tc_k<<<MLP_BLOCKS, 256, MLP_SMEM>>>(b1, b2, 2, 1, 0);
    // layer 2: g_f2 -> g_f1 = MID only (GEMM2 folded into classifier)
    agg_k<<<AGG_BLOCKS, 256>>>(2, x);
    mlp_tc_k<<<MLP_BLOCKS, 256, MLP_SMEM>>>(b1, b2, 1, 0, 1);

    pool_k<<<N_GRAPHS, HIDDEN>>>(batch);
    final_k<<<(N_GRAPHS * N_CLASSES + 255) / 256, 256>>>(out);
}

// round 17
// speedup vs baseline: 1.8741x; 1.1028x over previous
#include <cuda_runtime.h>
#include <cuda_fp16.h>
#include <cstdint>

#define N_NODES  50000
#define N_EDGES  800000
#define HIDDEN   128
#define N_GRAPHS 256
#define N_CLASSES 10
#define ELL_CAP  96   // max in-degree capacity; P(deg>=96) ~ 1e-40 for Poisson(16)

// -------- device scratch (no allocations allowed) --------
__device__ __align__(16) float g_agg[N_NODES * HIDDEN];
__device__ __align__(16) float g_f1[N_NODES * HIDDEN];
__device__ __align__(16) float g_f2[N_NODES * HIDDEN];
__device__ int   g_deg[N_NODES];
__device__ int   g_ell[N_NODES * ELL_CAP];
__device__ __align__(16) float g_pooled[N_GRAPHS * HIDDEN];
// folded classifier: Wc = W2 @ Wl (128x10), bc = b2 @ Wl + bl (10)
__device__ __align__(16) float g_Wc[HIDDEN * N_CLASSES];
__device__ float g_bc[N_CLASSES];
// fp16 weights, TRANSPOSED to [n][k] (built once per call)
__device__ __align__(16) __half g_W1T[HIDDEN * HIDDEN];
__device__ __align__(16) __half g_W2T[HIDDEN * HIDDEN];

__device__ __forceinline__ const float* pick_feat(int sel, const float* x) {
    return sel == 0 ? x : (sel == 1 ? g_f1 : g_f2);
}
__device__ __forceinline__ float* pick_out(int sel) {
    return sel == 1 ? g_f1 : g_f2;
}
__device__ __forceinline__ int clamp_node(int v) {
    v = v < 0 ? 0 : v;
    return v >= N_NODES ? N_NODES - 1 : v;
}
__device__ __forceinline__ uint32_t smem_u32(const void* p) {
    uint32_t a;
    asm("{ .reg .u64 t; cvta.to.shared.u64 t, %1; cvt.u32.u64 %0, t; }" : "=r"(a) : "l"(p));
    return a;
}

// ---------------- merged prep: zero_deg + split_w + fold_wc ----------------
#define ZERO_BLKS 196
#define SPLIT_BLKS 64
__global__ void prep1_k(const float* __restrict__ W1, const float* __restrict__ W2,
                        const float* __restrict__ b2, const float* __restrict__ Wl,
                        const float* __restrict__ bl) {
    int b = blockIdx.x;
    int tid = threadIdx.x;
    if (b < ZERO_BLKS) {
        int i = b * 256 + tid;
        if (i < N_NODES) g_deg[i] = 0;
    } else if (b < ZERO_BLKS + SPLIT_BLKS) {
        int i = (b - ZERO_BLKS) * 256 + tid;   // i = n*128 + k
        int n = i >> 7, k = i & 127;
        g_W1T[i] = __float2half_rn(W1[k * HIDDEN + n]);
        g_W2T[i] = __float2half_rn(W2[k * HIDDEN + n]);
    } else {
        int gw = (b - ZERO_BLKS - SPLIT_BLKS) * 8 + (tid >> 5);
        int lane = tid & 31;
        if (gw < HIDDEN) {
            int j = gw;
            float w0 = W2[j * HIDDEN + lane];
            float w1 = W2[j * HIDDEN + lane + 32];
            float w2 = W2[j * HIDDEN + lane + 64];
            float w3 = W2[j * HIDDEN + lane + 96];
#pragma unroll
            for (int c = 0; c < N_CLASSES; c++) {
                float v = w0 * Wl[lane * N_CLASSES + c]
                        + w1 * Wl[(lane + 32) * N_CLASSES + c]
                        + w2 * Wl[(lane + 64) * N_CLASSES + c]
                        + w3 * Wl[(lane + 96) * N_CLASSES + c];
#pragma unroll
                for (int s = 16; s > 0; s >>= 1)
                    v += __shfl_down_sync(0xffffffffu, v, s);
                if (lane == 0) g_Wc[j * N_CLASSES + c] = v;
            }
        } else if (gw < HIDDEN + N_CLASSES) {
            int c = gw - HIDDEN;
            float v = b2[lane]      * Wl[lane * N_CLASSES + c]
                    + b2[lane + 32] * Wl[(lane + 32) * N_CLASSES + c]
                    + b2[lane + 64] * Wl[(lane + 64) * N_CLASSES + c]
                    + b2[lane + 96] * Wl[(lane + 96) * N_CLASSES + c];
#pragma unroll
            for (int s = 16; s > 0; s >>= 1)
                v += __shfl_down_sync(0xffffffffu, v, s);
            if (lane == 0) g_bc[c] = v + bl[c];
        }
    }
}

// ---------------- ELL adjacency build: single pass, no scan ----------------
__global__ void fill_ell_k(const int* __restrict__ ei) {
    int e = blockIdx.x * blockDim.x + threadIdx.x;
    if (e < N_EDGES) {
        int s = clamp_node(ei[e]);
        int d = clamp_node(ei[N_EDGES + e]);
        int slot = atomicAdd(&g_deg[d], 1);
        if (slot < ELL_CAP) g_ell[d * ELL_CAP + slot] = s;
    }
}

// ---------------- edge aggregation: warp per node ----------------
__global__ void agg_k(int insel, const float* __restrict__ x) {
    int w    = (blockIdx.x * blockDim.x + threadIdx.x) >> 5;
    int lane = threadIdx.x & 31;
    if (w >= N_NODES) return;
    const float* feat = pick_feat(insel, x);
    int deg = g_deg[w];
    if (deg > ELL_CAP) deg = ELL_CAP;
    const int* row = &g_ell[w * ELL_CAP];
    const float4* f4 = (const float4*)feat;
    float4 acc = f4[w * 32 + lane];   // self feature
    int j = 0;
    for (; j + 1 < deg; j += 2) {
        int s0 = row[j], s1 = row[j + 1];
        float4 v0 = f4[s0 * 32 + lane];
        float4 v1 = f4[s1 * 32 + lane];
        acc.x += v0.x + v1.x; acc.y += v0.y + v1.y;
        acc.z += v0.z + v1.z; acc.w += v0.w + v1.w;
    }
    if (j < deg) {
        float4 v = f4[row[j] * 32 + lane];
        acc.x += v.x; acc.y += v.y; acc.z += v.z; acc.w += v.w;
    }
    ((float4*)g_agg)[w * 32 + lane] = acc;
}

// ---------------- tensor-core fused 2-layer MLP (fp16 + ldmatrix) ----------------
// out ≈ fp16(x) @ fp16(W): single-pass HMMA, f32 accum
// block: 64 nodes x 128 cols, 256 threads (8 warps = 2m x 4n, warp tile 32x32)
// 4 CTAs/SM: smem = INP 64x136 fp16 (17408) + WT 128x136 fp16 full-K (34816) = 52224
#define M_TILE 64
#define INP_S 136   // fp16 stride: row stride 272B -> ldmatrix conflict-free
#define WT_S  136   // fp16 stride, full K=128 per n-row
#define OUT_S 132   // f32 stride for epilogue staging

#define MMA_FP16(C, A0, A1, A2, A3, B0, B1)                                 \
    asm volatile(                                                           \
        "mma.sync.aligned.m16n8k16.row.col.f32.f16.f16.f32 "                \
        "{%0,%1,%2,%3}, {%4,%5,%6,%7}, {%8,%9}, {%0,%1,%2,%3};"             \
        : "+f"(C[0]), "+f"(C[1]), "+f"(C[2]), "+f"(C[3])                    \
        : "r"(A0), "r"(A1), "r"(A2), "r"(A3), "r"(B0), "r"(B1))

#define LDSM_X4(R0, R1, R2, R3, ADDR)                                       \
    asm volatile("ldmatrix.sync.aligned.m8n8.x4.shared.b16 {%0,%1,%2,%3}, [%4];" \
        : "=r"(R0), "=r"(R1), "=r"(R2), "=r"(R3) : "r"(ADDR))

__device__ __forceinline__ uint32_t pack_h2(float a, float b) {
    __half2 t = __floats2half2_rn(a, b);
    return *(uint32_t*)&t;
}

// one k16 step: A 2 LDSM.x4 (2 m-frags), B 2 LDSM.x4 (2 n-groups), 8 MMA
__device__ __forceinline__ void mma_kstep_ldsm(
        uint32_t aB,          // per-thread A base addr (mt=0)
        uint32_t bB,          // per-thread B base addr (g=0)
        int kk, float acc[2][4][4]) {
    const uint32_t MT_OFF = 16 * INP_S * 2;
    uint32_t a[2][4];
#pragma unroll
    for (int mt = 0; mt < 2; mt++)
        LDSM_X4(a[mt][0], a[mt][1], a[mt][2], a[mt][3], aB + mt * MT_OFF + kk * 2);
#pragma unroll
    for (int g = 0; g < 2; g++) {
        uint32_t boff = g * (16 * WT_S * 2) + kk * 2;
        uint32_t b0, b1, b2, b3;
        LDSM_X4(b0, b1, b2, b3, bB + boff);
#pragma unroll
        for (int mt = 0; mt < 2; mt++) {
            MMA_FP16(acc[mt][2 * g],     a[mt][0], a[mt][1], a[mt][2], a[mt][3], b0, b1);
            MMA_FP16(acc[mt][2 * g + 1], a[mt][0], a[mt][1], a[mt][2], a[mt][3], b2, b3);
        }
    }
}

// skip2 == 0: out = relu?((relu(INP@W1+b1))@W2+b2)
// skip2 == 1: out = relu(INP@W1+b1)           (GEMM2 folded into classifier)
__global__ void __launch_bounds__(256, 4) mlp_tc_k(
        const float* __restrict__ b1, const float* __restrict__ b2,
        int outsel, int do_relu, int skip2) {
    extern __shared__ char smraw[];
    __half* INP = (__half*)smraw;                    // 64*136*2 = 17408
    __half* WT  = INP + M_TILE * INP_S;              // 128*136*2 = 34816
    float* FOUT = (float*)smraw;  // overlays INP+WT after final MMA (33792 <= 52224)

    float* out = pick_out(outsel);

    int tid = threadIdx.x;
    int lane = tid & 31, warp = tid >> 5;
    int base = blockIdx.x * M_TILE;
    const int wm = (warp >> 2) * 32;   // 0,32
    const int wn = (warp & 3) * 32;    // 0,32,64,96

    // per-thread ldmatrix row addresses
    // A x4 quadrants: m0=(r,k) m1=(r+8,k) m2=(r,k+8) m3=(r+8,k+8)
    int a_row = wm + (lane & 7) + ((lane >> 3) & 1) * 8;
    int a_k   = (lane >> 4) * 8;
    uint32_t INP_u = smem_u32(INP);
    uint32_t WT_u  = smem_u32(WT);
    uint32_t aB = INP_u + (a_row * INP_S + a_k) * 2;
    // B x4 quadrants (group g): m0=(n2g,k) m1=(n2g,k+8) m2=(n2g+1,k) m3=(n2g+1,k+8)
    int b_row = wn + (lane & 7) + ((lane >> 4) & 1) * 8;
    int b_k   = ((lane >> 3) & 1) * 8;
    uint32_t bB = WT_u + (b_row * WT_S + b_k) * 2;

    // load INP = fp16(g_agg) (zero-pad tail rows); stage W1 full-K
    for (int i = tid; i < M_TILE * 32; i += 256) {
        int row = i >> 5, c4 = i & 31;
        int node = base + row;
        float4 v = make_float4(0.f, 0.f, 0.f, 0.f);
        if (node < N_NODES)
            v = ((const float4*)g_agg)[node * 32 + c4];
        *(uint2*)&INP[row * INP_S + c4 * 4] =
            make_uint2(pack_h2(v.x, v.y), pack_h2(v.z, v.w));
    }
    for (int i = tid; i < 128 * 16; i += 256) {   // 16 uint4 per n-row (128 fp16)
        int n = i >> 4, q = i & 15;
        *(uint4*)&WT[n * WT_S + q * 8] = *(const uint4*)&g_W1T[n * HIDDEN + q * 8];
    }
    __syncthreads();

    float acc[2][4][4];
#pragma unroll
    for (int mt = 0; mt < 2; mt++)
#pragma unroll
        for (int nt = 0; nt < 4; nt++)
#pragma unroll
            for (int r = 0; r < 4; r++) acc[mt][nt][r] = 0.f;

    // ---- GEMM 1: INP @ W1 (8 k16 steps, W staged once) ----
#pragma unroll
    for (int ks = 0; ks < 8; ks++)
        mma_kstep_ldsm(aB, bB, ks * 16, acc);
    __syncthreads();  // all INP/WT reads done

    if (skip2) {
        // out = relu(acc + b1) directly (FOUT overlays, safe after sync)
#pragma unroll
        for (int mt = 0; mt < 2; mt++) {
            int row = wm + mt * 16 + (lane >> 2);
#pragma unroll
            for (int nt = 0; nt < 4; nt++) {
                int col = wn + nt * 8 + 2 * (lane & 3);
                float2 bb = *(const float2*)(b1 + col);
                float2 v0, v1;
                v0.x = fmaxf(acc[mt][nt][0] + bb.x, 0.f);
                v0.y = fmaxf(acc[mt][nt][1] + bb.y, 0.f);
                v1.x = fmaxf(acc[mt][nt][2] + bb.x, 0.f);
                v1.y = fmaxf(acc[mt][nt][3] + bb.y, 0.f);
                *(float2*)&FOUT[row * OUT_S + col] = v0;
                *(float2*)&FOUT[(row + 8) * OUT_S + col] = v1;
            }
        }
        __syncthreads();
        for (int i = tid; i < M_TILE * 32; i += 256) {
            int row2 = i >> 5, c4 = i & 31;
            int node = base + row2;
            if (node < N_NODES)
                ((float4*)out)[node * 32 + c4] = *(float4*)&FOUT[row2 * OUT_S + c4 * 4];
        }
        return;
    }

    // MID = fp16(relu(acc + b1)) -> overwrite INP; stage W2
#pragma unroll
    for (int mt = 0; mt < 2; mt++) {
        int row = wm + mt * 16 + (lane >> 2);
#pragma unroll
        for (int nt = 0; nt < 4; nt++) {
            int col = wn + nt * 8 + 2 * (lane & 3);
            float2 bb = *(const float2*)(b1 + col);
            float m0 = fmaxf(acc[mt][nt][0] + bb.x, 0.f);
            float m1 = fmaxf(acc[mt][nt][1] + bb.y, 0.f);
            float m2 = fmaxf(acc[mt][nt][2] + bb.x, 0.f);
            float m3 = fmaxf(acc[mt][nt][3] + bb.y, 0.f);
            *(uint32_t*)&INP[row * INP_S + col]       = pack_h2(m0, m1);
            *(uint32_t*)&INP[(row + 8) * INP_S + col] = pack_h2(m2, m3);
        }
    }
    for (int i = tid; i < 128 * 16; i += 256) {
        int n = i >> 4, q = i & 15;
        *(uint4*)&WT[n * WT_S + q * 8] = *(const uint4*)&g_W2T[n * HIDDEN + q * 8];
    }

#pragma unroll
    for (int mt = 0; mt < 2; mt++)
#pragma unroll
        for (int nt = 0; nt < 4; nt++)
#pragma unroll
            for (int r = 0; r < 4; r++) acc[mt][nt][r] = 0.f;

    __syncthreads();  // MID + W2 visible

    // ---- GEMM 2: MID @ W2 ----
#pragma unroll
    for (int ks = 0; ks < 8; ks++)
        mma_kstep_ldsm(aB, bB, ks * 16, acc);
    __syncthreads();  // all reads done -> FOUT may overlay

    // OUT = (acc + b2) [relu?] -> f32 staging, then coalesced copy out
#pragma unroll
    for (int mt = 0; mt < 2; mt++) {
        int row = wm + mt * 16 + (lane >> 2);
#pragma unroll
        for (int nt = 0; nt < 4; nt++) {
            int col = wn + nt * 8 + 2 * (lane & 3);
            float2 bb = *(const float2*)(b2 + col);
            float2 v0, v1;
            v0.x = acc[mt][nt][0] + bb.x;
            v0.y = acc[mt][nt][1] + bb.y;
            v1.x = acc[mt][nt][2] + bb.x;
            v1.y = acc[mt][nt][3] + bb.y;
            if (do_relu) {
                v0.x = fmaxf(v0.x, 0.f); v0.y = fmaxf(v0.y, 0.f);
                v1.x = fmaxf(v1.x, 0.f); v1.y = fmaxf(v1.y, 0.f);
            }
            *(float2*)&FOUT[row * OUT_S + col] = v0;
            *(float2*)&FOUT[(row + 8) * OUT_S + col] = v1;
        }
    }
    __syncthreads();

    for (int i = tid; i < M_TILE * 32; i += 256) {
        int row = i >> 5, c4 = i & 31;
        int node = base + row;
        if (node < N_NODES)
            ((float4*)out)[node * 32 + c4] = *(float4*)&FOUT[row * OUT_S + c4 * 4];
    }
}

// ---------------- mean pool per graph (batch is sorted, int32) ----------------
__device__ __forceinline__ int lb_batch(const int* b, int v) {
    int lo = 0, hi = N_NODES;
    while (lo < hi) {
        int m = (lo + hi) >> 1;
        if (b[m] < v) lo = m + 1; else hi = m;
    }
    return lo;
}

__global__ void pool_k(const int* __restrict__ batch) {
    int g = blockIdx.x;
    int t = threadIdx.x;
    int lo = lb_batch(batch, g);
    int hi = lb_batch(batch, g + 1);
    float s = 0.f;
    for (int n = lo; n < hi; n++) s += g_f1[n * HIDDEN + t];
    int cnt = hi - lo;
    float c = (float)(cnt > 0 ? cnt : 1);
    g_pooled[g * HIDDEN + t] = s / c;
}

// ---------------- final classifier: pooled @ Wc + bc ----------------
__global__ void final_k(float* __restrict__ out) {
    int i = blockIdx.x * blockDim.x + threadIdx.x;
    if (i < N_GRAPHS * N_CLASSES) {
        int g = i / N_CLASSES, c = i % N_CLASSES;
        float s = g_bc[c];
        const float* p = &g_pooled[g * HIDDEN];
        for (int k = 0; k < HIDDEN; k++) s += p[k] * g_Wc[k * N_CLASSES + c];
        out[i] = s;
    }
}

// ---------------- launcher ----------------
extern "C" void kernel_launch(void* const* d_in, const int* in_sizes, int n_in,
                              void* d_out, int out_size) {
    const float* x     = (const float*)d_in[0];
    const int*   ei    = (const int*)d_in[1];
    const int*   batch = (const int*)d_in[2];
    const float* W1    = (const float*)d_in[3];
    const float* b1    = (const float*)d_in[4];
    const float* W2    = (const float*)d_in[5];
    const float* b2    = (const float*)d_in[6];
    const float* Wl    = (const float*)d_in[7];
    const float* bl    = (const float*)d_in[8];
    float* out = (float*)d_out;

    const int MLP_SMEM = (M_TILE * INP_S + 128 * WT_S) * 2;  // 52224 B
    cudaFuncSetAttribute(mlp_tc_k, cudaFuncAttributeMaxDynamicSharedMemorySize, MLP_SMEM);

    // prep: zero+cast+fold, then single-pass ELL build (no scan, no hist)
    prep1_k<<<ZERO_BLKS + SPLIT_BLKS + 18, 256>>>(W1, W2, b2, Wl, bl);
    fill_ell_k<<<(N_EDGES + 255) / 256, 256>>>(ei);

    const int AGG_BLOCKS = (N_NODES * 32 + 255) / 256;
    const int MLP_BLOCKS = (N_NODES + M_TILE - 1) / M_TILE;   // 782

    // layer 0: x -> g_f1 (relu)
    agg_k<<<AGG_BLOCKS, 256>>>(0, x);
    mlp_tc_k<<<MLP_BLOCKS, 256, MLP_SMEM>>>(b1, b2, 1, 1, 0);
    // layer 1: g_f1 -> g_f2 (relu)
    agg_k<<<AGG_BLOCKS, 256>>>(1, x);
    mlp_tc_k<<<MLP_BLOCKS, 256, MLP_SMEM>>>(b1, b2, 2, 1, 0);
    // layer 2: g_f2 -> g_f1 = MID only (GEMM2 folded into classifier)
    agg_k<<<AGG_BLOCKS, 256>>>(2, x);
    mlp_tc_k<<<MLP_BLOCKS, 256, MLP_SMEM>>>(b1, b2, 1, 0, 1);

    pool_k<<<N_GRAPHS, HIDDEN>>>(batch);
    final_k<<<(N_GRAPHS * N_CLASSES + 255) / 256, 256>>>(out);
}